// round 12
// baseline (speedup 1.0000x reference)
#include <cuda_runtime.h>
#include <cstdint>

// CELossWithLS: focal-weighted label-smoothed CE. Single fused kernel,
// TMA-bulk smem staging + zero-pressure atomic epilogue.
// logits: [B*S, C] f32 (C = 10000), target: [B*S] int32, out: scalar f32.
//
// per_tok = -( 1e-5 * sum_i (1-p_i)^3 * logs_i  +  0.9 * (1-p_t)^3 * logs_t )
// sum_i (1-p)^3 logs = (Sx - C*L) - 3*(B1/A1 - L) + O(1.5e-5 abs),
// A1 = sum e^x, B1 = sum x e^x, L = log(A1). rel_err <= 2e-6 measured.
//
// r3-r11 conclusion: register-resident LDG streaming saturates at ~6.0-6.4
// TB/s here; ptxas (regs=30) refuses to batch 2 LDG.128 and source-level
// tricks don't override it. This round changes the TRANSPORT: cp.async.bulk
// stages the whole 40000B row into smem as 4 x 10000B chunks (own mbarrier
// each, issued back-to-back at CTA start); consumers process chunk c while
// c+1..3 land. In-flight bytes/SM: 5 CTAs x 40KB = 200KB, decoupled from
// registers. Target gather now reads smem; __logf shortens the warp-0 tail.

#define NCLASS   10000
#define ROWBYTES (NCLASS * 4)        // 40000
#define NCHUNK   4
#define CHUNKB   (ROWBYTES / NCHUNK) // 10000 (multiple of 16)
#define CHUNKV   (CHUNKB / 16)       // 625 float4
#define THREADS  256

__device__ float              g_sum  = 0.0f;  // reset by last CTA each call
__device__ unsigned long long g_pack = 0ull;  // hi: arrivals, lo: valid count

__device__ __forceinline__ uint32_t s2u(const void* p) {
    return (uint32_t)__cvta_generic_to_shared(p);
}

__device__ __forceinline__ void mbar_init(uint32_t mbar, uint32_t cnt) {
    asm volatile("mbarrier.init.shared.b64 [%0], %1;" :: "r"(mbar), "r"(cnt) : "memory");
}
__device__ __forceinline__ void mbar_expect_tx(uint32_t mbar, uint32_t bytes) {
    asm volatile("mbarrier.arrive.expect_tx.shared.b64 _, [%0], %1;"
                 :: "r"(mbar), "r"(bytes) : "memory");
}
__device__ __forceinline__ void bulk_g2s(uint32_t sdst, const void* gsrc,
                                         uint32_t bytes, uint32_t mbar) {
    asm volatile(
        "cp.async.bulk.shared::cluster.global.mbarrier::complete_tx::bytes "
        "[%0], [%1], %2, [%3];"
        :: "r"(sdst), "l"(gsrc), "r"(bytes), "r"(mbar) : "memory");
}
__device__ __forceinline__ void mbar_wait(uint32_t mbar, uint32_t parity) {
    asm volatile(
        "{\n\t"
        ".reg .pred P;\n\t"
        "W_%=:\n\t"
        "mbarrier.try_wait.parity.acquire.cta.shared::cta.b64 P, [%0], %1, 0x989680;\n\t"
        "@P bra.uni D_%=;\n\t"
        "bra.uni W_%=;\n\t"
        "D_%=:\n\t"
        "}"
        :: "r"(mbar), "r"(parity) : "memory");
}

__device__ __forceinline__ void proc4(const float4 v,
                                      float& sx, float& a1, float& b1) {
    float e;
    e = __expf(v.x); sx += v.x; a1 += e; b1 = fmaf(v.x, e, b1);
    e = __expf(v.y); sx += v.y; a1 += e; b1 = fmaf(v.y, e, b1);
    e = __expf(v.z); sx += v.z; a1 += e; b1 = fmaf(v.z, e, b1);
    e = __expf(v.w); sx += v.w; a1 += e; b1 = fmaf(v.w, e, b1);
}

__global__ __launch_bounds__(THREADS, 1) void ce_fused(
    const float* __restrict__ logits,
    const int*   __restrict__ target,
    float*       __restrict__ out,
    const int    ntok)
{
    __shared__ __align__(128) unsigned char buf[ROWBYTES];   // whole row
    __shared__ __align__(8)   unsigned long long mbar_s[NCHUNK];

    const int row = blockIdx.x;
    const int tgt = __ldg(&target[row]);

    const uint32_t buf_u  = s2u(buf);
    const uint32_t mbar_u = s2u(mbar_s);

    if (threadIdx.x == 0) {
        #pragma unroll
        for (int c = 0; c < NCHUNK; c++) mbar_init(mbar_u + 8 * c, 1);
    }
    __syncthreads();                              // inits visible to all

    if (threadIdx.x == 0) {
        const char* src = (const char*)logits + (size_t)row * ROWBYTES;
        #pragma unroll
        for (int c = 0; c < NCHUNK; c++) {
            mbar_expect_tx(mbar_u + 8 * c, CHUNKB);
            bulk_g2s(buf_u + c * CHUNKB, src + (size_t)c * CHUNKB,
                     CHUNKB, mbar_u + 8 * c);
        }
    }

    float sx = 0.0f, a1 = 0.0f, b1 = 0.0f;
    #pragma unroll
    for (int c = 0; c < NCHUNK; c++) {
        mbar_wait(mbar_u + 8 * c, 0);             // acquire: smem reads ordered
        const float4* pb = reinterpret_cast<const float4*>(buf + c * CHUNKB);
        for (int j = threadIdx.x; j < CHUNKV; j += THREADS)
            proc4(pb[j], sx, a1, b1);
    }

    // intra-warp tree reduce (3 values)
    #pragma unroll
    for (int o = 16; o > 0; o >>= 1) {
        sx += __shfl_down_sync(0xffffffffu, sx, o);
        a1 += __shfl_down_sync(0xffffffffu, a1, o);
        b1 += __shfl_down_sync(0xffffffffu, b1, o);
    }

    __shared__ float s_sx[THREADS / 32];
    __shared__ float s_a1[THREADS / 32];
    __shared__ float s_b1[THREADS / 32];
    const int lane = threadIdx.x & 31;
    const int wrp  = threadIdx.x >> 5;
    if (lane == 0) { s_sx[wrp] = sx; s_a1[wrp] = a1; s_b1[wrp] = b1; }
    __syncthreads();

    if (threadIdx.x == 0) {
        float SX = 0.0f, A1 = 0.0f, B1 = 0.0f;
        #pragma unroll
        for (int k = 0; k < THREADS / 32; k++) {
            SX += s_sx[k]; A1 += s_a1[k]; B1 += s_b1[k];
        }

        unsigned valid = 0u;
        if (tgt != -1) {
            // __logf: ~1e-6 abs error in L -> ~1e-7 rel in per_tok; shortens
            // the serialized warp-0 tail vs software logf.
            float L  = __logf(A1);
            float S3 = (SX - (float)NCLASS * L) - 3.0f * (B1 / A1 - L);
            float per_tok = -1e-5f * S3;
            if (tgt >= 0 && tgt < NCLASS) {
                // row is smem-resident: free gather, no gmem round-trip
                float xt = *reinterpret_cast<const float*>(buf + 4 * tgt);
                float lt = xt - L;
                float pt = __expf(lt);
                float om = 1.0f - pt;
                per_tok -= 0.9f * om * om * om * lt;
            }
            atomicAdd(&g_sum, per_tok);
            valid = 1u;
        }

        __threadfence();                          // sum-add before pack-add
        unsigned long long prev =
            atomicAdd(&g_pack, 0x100000000ull + (unsigned long long)valid);
        unsigned arrived = (unsigned)(prev >> 32);

        if (arrived == (unsigned)(ntok - 1)) {    // I am the last CTA
            __threadfence();                      // acquire all sum-adds
            unsigned cnt = (unsigned)(prev & 0xffffffffu) + valid;
            float total = atomicExch(&g_sum, 0.0f);   // read + reset
            out[0] = total / (float)cnt;
            g_pack = 0ull;                        // reset for next replay
        }
    }
}

extern "C" void kernel_launch(void* const* d_in, const int* in_sizes, int n_in,
                              void* d_out, int out_size)
{
    const float* logits = (const float*)d_in[0];
    const int*   target = (const int*)d_in[1];
    const int ntok = in_sizes[1];          // B*S tokens

    ce_fused<<<ntok, THREADS>>>(logits, target, (float*)d_out, ntok);
}

// round 13
// speedup vs baseline: 1.1101x; 1.1101x over previous
#include <cuda_runtime.h>

// CELossWithLS: focal-weighted label-smoothed CE, single fused kernel.
// logits: [B*S, C] f32 (C = 10000), target: [B*S] int32, out: scalar f32.
//
// per_tok = -( 1e-5 * sum_i (1-p_i)^3 * logs_i  +  0.9 * (1-p_t)^3 * logs_t )
// sum_i (1-p)^3 logs = (Sx - C*L) - 3*(B1/A1 - L) + O(1.5e-5 abs),
// A1 = sum e^x, B1 = sum x e^x, L = log(A1). rel_err <= 2e-6 measured.
//
// r12 finding: TMA smem staging LOSES (62us, lockstep chunk barriers + occ
// 38%) -> register LDG streaming is the right transport. Key diagnosis this
// round: fused kernels (55us) vs identical standalone loop (51us) differ by
// exactly two __threadfence() per CTA -- gpu-scope fence emits CCTL.IVALL =
// full L1D flush, 16384 of them disrupting co-resident CTAs. Replace with
// PTX memory-order atomics (no fence instruction, no L1 flush):
//   red.relaxed.gpu.add.f32            per-token sum (REDG, no return)
//   atom.acq_rel.gpu.add.u64           packed arrive|valid counter
//   atom.acquire.gpu.exch.b32          last-CTA read+reset of the sum
// Also: target-logit load hoisted to kernel entry (latency overlaps the
// streaming loop instead of the serialized warp-0 tail); __logf (validated).

#define NCLASS  10000
#define NVEC    (NCLASS / 4)   // 2500 float4 per row
#define THREADS 256

__device__ float              g_sum  = 0.0f;  // reset by last CTA each call
__device__ unsigned long long g_pack = 0ull;  // hi: arrivals, lo: valid count

__device__ __forceinline__ void red_add_f32_relaxed(float* p, float v) {
    asm volatile("red.relaxed.gpu.add.f32 [%0], %1;" :: "l"(p), "f"(v) : "memory");
}
__device__ __forceinline__ unsigned long long
atom_add_u64_acqrel(unsigned long long* p, unsigned long long v) {
    unsigned long long r;
    asm volatile("atom.acq_rel.gpu.add.u64 %0, [%1], %2;"
                 : "=l"(r) : "l"(p), "l"(v) : "memory");
    return r;
}
__device__ __forceinline__ float atom_exch_f32_acquire(float* p, float v) {
    float r;
    asm volatile("atom.acquire.gpu.exch.b32 %0, [%1], %2;"
                 : "=f"(r) : "l"(p), "f"(v) : "memory");
    return r;
}

__device__ __forceinline__ void proc4(const float4 v,
                                      float& sx, float& a1, float& b1) {
    float e;
    e = __expf(v.x); sx += v.x; a1 += e; b1 = fmaf(v.x, e, b1);
    e = __expf(v.y); sx += v.y; a1 += e; b1 = fmaf(v.y, e, b1);
    e = __expf(v.z); sx += v.z; a1 += e; b1 = fmaf(v.z, e, b1);
    e = __expf(v.w); sx += v.w; a1 += e; b1 = fmaf(v.w, e, b1);
}

__global__ __launch_bounds__(THREADS, 1) void ce_fused(
    const float* __restrict__ logits,
    const int*   __restrict__ target,
    float*       __restrict__ out,
    const int    ntok)
{
    const int row = blockIdx.x;
    const int tgt = __ldg(&target[row]);

    // Hoisted target-logit load: latency overlaps the whole streaming loop.
    // Uniform address across the warp -> single broadcast LDG.
    float xt = 0.0f;
    if (tgt >= 0 && tgt < NCLASS)
        xt = __ldg(&logits[(size_t)row * NCLASS + tgt]);

    const float4* __restrict__ p =
        reinterpret_cast<const float4*>(logits) + (size_t)row * NVEC;

    float sx = 0.0f;   // sum x
    float a1 = 0.0f;   // sum e^x
    float b1 = 0.0f;   // sum x * e^x

    #pragma unroll 2
    for (int i = threadIdx.x; i < NVEC; i += THREADS) {
        float4 v = __ldcs(&p[i]);
        proc4(v, sx, a1, b1);
    }

    // intra-warp tree reduce (3 values)
    #pragma unroll
    for (int o = 16; o > 0; o >>= 1) {
        sx += __shfl_down_sync(0xffffffffu, sx, o);
        a1 += __shfl_down_sync(0xffffffffu, a1, o);
        b1 += __shfl_down_sync(0xffffffffu, b1, o);
    }

    __shared__ float s_sx[THREADS / 32];
    __shared__ float s_a1[THREADS / 32];
    __shared__ float s_b1[THREADS / 32];
    const int lane = threadIdx.x & 31;
    const int wrp  = threadIdx.x >> 5;
    if (lane == 0) { s_sx[wrp] = sx; s_a1[wrp] = a1; s_b1[wrp] = b1; }
    __syncthreads();

    if (threadIdx.x == 0) {
        float SX = 0.0f, A1 = 0.0f, B1 = 0.0f;
        #pragma unroll
        for (int k = 0; k < THREADS / 32; k++) {
            SX += s_sx[k]; A1 += s_a1[k]; B1 += s_b1[k];
        }

        unsigned valid = 0u;
        if (tgt != -1) {
            float L  = __logf(A1);
            float S3 = (SX - (float)NCLASS * L) - 3.0f * (B1 / A1 - L);
            float per_tok = -1e-5f * S3;
            if (tgt >= 0 && tgt < NCLASS) {
                float lt = xt - L;
                float pt = __expf(lt);
                float om = 1.0f - pt;
                per_tok -= 0.9f * om * om * om * lt;
            }
            red_add_f32_relaxed(&g_sum, per_tok);   // REDG, no fence needed
            valid = 1u;
        }

        // acq_rel: release orders my g_sum red before my arrival;
        // acquire (for the last arriver) makes ALL g_sum reds visible.
        unsigned long long prev =
            atom_add_u64_acqrel(&g_pack, 0x100000000ull + (unsigned long long)valid);
        unsigned arrived = (unsigned)(prev >> 32);

        if (arrived == (unsigned)(ntok - 1)) {      // I am the last CTA
            unsigned cnt = (unsigned)(prev & 0xffffffffu) + valid;
            float total = atom_exch_f32_acquire(&g_sum, 0.0f);  // read + reset
            out[0] = total / (float)cnt;
            g_pack = 0ull;                          // reset for next replay
        }
    }
}

extern "C" void kernel_launch(void* const* d_in, const int* in_sizes, int n_in,
                              void* d_out, int out_size)
{
    const float* logits = (const float*)d_in[0];
    const int*   target = (const int*)d_in[1];
    const int ntok = in_sizes[1];          // B*S tokens

    ce_fused<<<ntok, THREADS>>>(logits, target, (float*)d_out, ntok);
}